// round 6
// baseline (speedup 1.0000x reference)
#include <cuda_runtime.h>
#include <cuda_bf16.h>
#include <cuda_fp16.h>
#include <math.h>
#include <stdint.h>

#define MAXN 100000
#define MAXE 1600000
#define HDIM 128
#define CDIM 40
#define NBLK ((MAXN + 255) / 256)
#define PAD 136  // halves per smem row (128 + 8 pad -> conflict-free ldmatrix)

// ---------------- device scratch ----------------
__device__ __half g_linh[MAXN * HDIM];        // norm[row]*(h@W) in fp16 (gather payload)
__device__ float  g_lin[MAXN * HDIM];         // fp32 logits (head)
__device__ float  g_h[MAXN * HDIM];           // layer output (post-ReLU), fp32
__device__ float  g_norm[MAXN];
__device__ int    g_deg[MAXN];
__device__ int    g_rowstart[MAXN + 1];
__device__ int    g_cursor[MAXN];
__device__ int    g_bsum[NBLK + 1];
__device__ int    g_csrS[MAXE];               // src index per edge, grouped by dst
__device__ float  g_Wf[HDIM * CDIM];
__device__ float  g_bf[CDIM];
__device__ int    g_any;                      // nonzero odd-word flag (int32 edges)
__device__ __nv_bfloat16 g_Bh[4 * HDIM * HDIM];  // W^T bf16 hi images (3 layers + head)
__device__ __nv_bfloat16 g_Bl[4 * HDIM * HDIM];  // lo residuals

// ---------------- PTX helpers ----------------
__device__ __forceinline__ uint32_t smem_u32(const void* p) {
    uint32_t a;
    asm("{ .reg .u64 t; cvta.to.shared.u64 t, %1; cvt.u32.u64 %0, t; }" : "=r"(a) : "l"(p));
    return a;
}
__device__ __forceinline__ void ldx4(uint32_t* r, uint32_t addr) {
    asm volatile("ldmatrix.sync.aligned.m8n8.x4.shared.b16 {%0,%1,%2,%3}, [%4];"
                 : "=r"(r[0]), "=r"(r[1]), "=r"(r[2]), "=r"(r[3]) : "r"(addr));
}
__device__ __forceinline__ void mma_bf16(float* d, const uint32_t* a, const uint32_t* b) {
    asm volatile("mma.sync.aligned.m16n8k16.row.col.f32.bf16.bf16.f32 "
                 "{%0,%1,%2,%3}, {%4,%5,%6,%7}, {%8,%9}, {%0,%1,%2,%3};"
                 : "+f"(d[0]), "+f"(d[1]), "+f"(d[2]), "+f"(d[3])
                 : "r"(a[0]), "r"(a[1]), "r"(a[2]), "r"(a[3]), "r"(b[0]), "r"(b[1]));
}

__device__ __forceinline__ int load_node(const void* ei, long long i, int is64) {
    if (is64) return (int)((const long long*)ei)[i];
    return ((const int*)ei)[i];
}

// ---------------- init: zero deg + g_any ----------------
__global__ void init_kernel(int M) {
    int i = blockIdx.x * blockDim.x + threadIdx.x;
    if (i < M) g_deg[i] = 0;
    if (i == 0) g_any = 0;
}
__global__ void detect_kernel(const int* __restrict__ ei32, int nHalf) {
    int found = 0;
    for (int i = blockIdx.x * blockDim.x + threadIdx.x; i < nHalf; i += gridDim.x * blockDim.x)
        if (ei32[2 * i + 1] != 0) found = 1;
    if (found) atomicOr(&g_any, 1);
}
__global__ void count_deg_kernel(const void* __restrict__ ei, int E) {
    int is64 = (g_any == 0);
    int e = blockIdx.x * blockDim.x + threadIdx.x;
    if (e >= E) return;
    atomicAdd(&g_deg[load_node(ei, (long long)E + e, is64)], 1);
}
// norm + block sums in one pass
__global__ void norm_bsum_kernel(int M) {
    __shared__ int sd[256];
    int i = blockIdx.x * 256 + threadIdx.x;
    int d = (i < M) ? g_deg[i] : 0;
    if (i < M) g_norm[i] = rsqrtf((float)d + 1.0f);
    sd[threadIdx.x] = d;
    __syncthreads();
    for (int o = 128; o > 0; o >>= 1) {
        if (threadIdx.x < o) sd[threadIdx.x] += sd[threadIdx.x + o];
        __syncthreads();
    }
    if (threadIdx.x == 0) g_bsum[blockIdx.x] = sd[0];
}
__global__ void bscan_kernel(int nb) {
    __shared__ int sd[512];
    int t = threadIdx.x;
    int v = (t < nb) ? g_bsum[t] : 0;
    sd[t] = v;
    __syncthreads();
    for (int o = 1; o < 512; o <<= 1) {
        int x = (t >= o) ? sd[t - o] : 0;
        __syncthreads();
        sd[t] += x;
        __syncthreads();
    }
    if (t < nb) g_bsum[t] = sd[t] - v;
}
__global__ void rowstart_kernel(int M, int E) {
    __shared__ int sd[256];
    int i = blockIdx.x * 256 + threadIdx.x;
    int v = (i < M) ? g_deg[i] : 0;
    sd[threadIdx.x] = v;
    __syncthreads();
    for (int o = 1; o < 256; o <<= 1) {
        int t = (threadIdx.x >= o) ? sd[threadIdx.x - o] : 0;
        __syncthreads();
        sd[threadIdx.x] += t;
        __syncthreads();
    }
    if (i < M) {
        g_rowstart[i] = g_bsum[blockIdx.x] + sd[threadIdx.x] - v;
        g_cursor[i] = 0;
    }
    if (i == 0) g_rowstart[M] = E;
}
__global__ void csr_fill_kernel(const void* __restrict__ ei, int E) {
    int is64 = (g_any == 0);
    int e = blockIdx.x * blockDim.x + threadIdx.x;
    if (e >= E) return;
    int s = load_node(ei, e, is64);
    int d = load_node(ei, (long long)E + e, is64);
    int pos = g_rowstart[d] + atomicAdd(&g_cursor[d], 1);
    g_csrS[pos] = s;
}

// ---------------- fold MLP head: Wf = Wp1@Wp2, bf = bp1@Wp2 + bp2 ----------------
__global__ void fuse_wb_kernel(const float* __restrict__ Wp1, const float* __restrict__ bp1,
                               const float* __restrict__ Wp2, const float* __restrict__ bp2) {
    int id = blockIdx.x * blockDim.x + threadIdx.x;
    if (id < HDIM * CDIM) {
        int i = id / CDIM, c = id % CDIM;
        float s = 0.f;
        for (int j = 0; j < HDIM; j++)
            s = fmaf(Wp1[i * HDIM + j], Wp2[j * CDIM + c], s);
        g_Wf[id] = s;
    } else if (id < HDIM * CDIM + CDIM) {
        int c = id - HDIM * CDIM;
        float s = bp2[c];
        for (int j = 0; j < HDIM; j++)
            s = fmaf(bp1[j], Wp2[j * CDIM + c], s);
        g_bf[c] = s;
    }
}

// ---------------- W splits ----------------
__global__ void w_split_all_kernel(const float* __restrict__ W1, const float* __restrict__ W2,
                                   const float* __restrict__ W3) {
    int idx = blockIdx.x * 256 + threadIdx.x;
    if (idx >= 3 * HDIM * HDIM) return;
    int l = idx / (HDIM * HDIM);
    int r = idx - l * HDIM * HDIM;
    int n = r >> 7, k = r & 127;
    const float* W = (l == 0) ? W1 : (l == 1) ? W2 : W3;
    float v = W[k * HDIM + n];
    __nv_bfloat16 h = __float2bfloat16(v);
    g_Bh[idx] = h;
    g_Bl[idx] = __float2bfloat16(v - __bfloat162float(h));
}
__global__ void w_split_head_kernel() {
    int idx = blockIdx.x * 256 + threadIdx.x;
    if (idx >= HDIM * HDIM) return;
    int n = idx >> 7, k = idx & 127;
    float v = (n < CDIM) ? g_Wf[k * CDIM + n] : 0.f;
    __nv_bfloat16 h = __float2bfloat16(v);
    g_Bh[3 * HDIM * HDIM + idx] = h;
    g_Bl[3 * HDIM * HDIM + idx] = __float2bfloat16(v - __bfloat162float(h));
}

// ---------------- mma.sync GEMM (fp32 via bf16 hi/lo, 3 terms) ----------------
#define GEMM_SMEM (4 * 128 * PAD * 2)

__global__ __launch_bounds__(256) void mma_gemm_kernel(
    const float* __restrict__ A_ext, int M, int useInternal, int bsel, int mode)
{
    extern __shared__ __nv_bfloat16 sm[];
    __nv_bfloat16* sAh = sm;
    __nv_bfloat16* sAl = sm + 128 * PAD;
    __nv_bfloat16* sBh = sm + 2 * 128 * PAD;
    __nv_bfloat16* sBl = sm + 3 * 128 * PAD;
    const float* A = useInternal ? g_h : A_ext;
    const __nv_bfloat16* Bh = g_Bh + bsel * HDIM * HDIM;
    const __nv_bfloat16* Bl = g_Bl + bsel * HDIM * HDIM;

    int tid = threadIdx.x;
    int rowBase = blockIdx.x * 128;

    {
        const uint4* bh = (const uint4*)Bh;
        const uint4* bl = (const uint4*)Bl;
        for (int i = tid; i < 128 * 16; i += 256) {
            int n = i >> 4, c = i & 15;
            *(uint4*)(sBh + n * PAD + c * 8) = bh[i];
            *(uint4*)(sBl + n * PAD + c * 8) = bl[i];
        }
    }
    {
        int row = tid >> 1;
        int colBase = (tid & 1) * 64;
        int grow = rowBase + row;
        const float4* Ap = (const float4*)(A + (size_t)grow * HDIM + colBase);
        __nv_bfloat16* dh = sAh + row * PAD + colBase;
        __nv_bfloat16* dl = sAl + row * PAD + colBase;
        #pragma unroll
        for (int j = 0; j < 16; j++) {
            float4 v = make_float4(0.f, 0.f, 0.f, 0.f);
            if (grow < M) v = Ap[j];
            __nv_bfloat16 h0 = __float2bfloat16(v.x);
            __nv_bfloat16 h1 = __float2bfloat16(v.y);
            __nv_bfloat16 h2 = __float2bfloat16(v.z);
            __nv_bfloat16 h3 = __float2bfloat16(v.w);
            dh[j * 4 + 0] = h0; dh[j * 4 + 1] = h1;
            dh[j * 4 + 2] = h2; dh[j * 4 + 3] = h3;
            dl[j * 4 + 0] = __float2bfloat16(v.x - __bfloat162float(h0));
            dl[j * 4 + 1] = __float2bfloat16(v.y - __bfloat162float(h1));
            dl[j * 4 + 2] = __float2bfloat16(v.z - __bfloat162float(h2));
            dl[j * 4 + 3] = __float2bfloat16(v.w - __bfloat162float(h3));
        }
    }
    __syncthreads();

    int lane = tid & 31, wid = tid >> 5;
    int wm = (wid & 3) * 32;
    int wn = (wid >> 2) * 64;

    uint32_t sbase = smem_u32(sm);
    int a_r = lane & 15;
    int a_k = (lane >> 4) * 8;
    int b_n = ((lane >> 4) & 1) * 8 + (lane & 7);
    int b_k = ((lane >> 3) & 1) * 8;

    uint32_t aAh = sbase + ((wm + a_r) * PAD + a_k) * 2;
    uint32_t aAl = aAh + 128 * PAD * 2;
    uint32_t aBh = sbase + 2 * 128 * PAD * 2 + ((wn + b_n) * PAD + b_k) * 2;
    uint32_t aBl = aBh + 128 * PAD * 2;

    float d[2][8][4];
    #pragma unroll
    for (int mt = 0; mt < 2; mt++)
        #pragma unroll
        for (int nt = 0; nt < 8; nt++)
            #pragma unroll
            for (int r = 0; r < 4; r++) d[mt][nt][r] = 0.f;

    #pragma unroll
    for (int ks = 0; ks < 8; ks++) {
        uint32_t ah[2][4], al[2][4], bh[4][4], bl[4][4];
        uint32_t koff = (uint32_t)(ks * 16 * 2);
        #pragma unroll
        for (int mt = 0; mt < 2; mt++) {
            uint32_t moff = (uint32_t)(mt * 16 * PAD * 2) + koff;
            ldx4(ah[mt], aAh + moff);
            ldx4(al[mt], aAl + moff);
        }
        #pragma unroll
        for (int np = 0; np < 4; np++) {
            uint32_t noff = (uint32_t)(np * 16 * PAD * 2) + koff;
            ldx4(bh[np], aBh + noff);
            ldx4(bl[np], aBl + noff);
        }
        #pragma unroll
        for (int mt = 0; mt < 2; mt++) {
            #pragma unroll
            for (int nt = 0; nt < 8; nt++) {
                uint32_t* ph = &bh[nt >> 1][(nt & 1) * 2];
                uint32_t* pl = &bl[nt >> 1][(nt & 1) * 2];
                mma_bf16(d[mt][nt], ah[mt], ph);
                mma_bf16(d[mt][nt], ah[mt], pl);
                mma_bf16(d[mt][nt], al[mt], ph);
            }
        }
    }

    int g = lane >> 2, t2 = (lane & 3) * 2;
    #pragma unroll
    for (int mt = 0; mt < 2; mt++) {
        int r0 = rowBase + wm + mt * 16 + g;
        int r1 = r0 + 8;
        if (mode == 0) {
            float n0 = (r0 < M) ? g_norm[r0] : 0.f;
            float n1 = (r1 < M) ? g_norm[r1] : 0.f;
            #pragma unroll
            for (int nt = 0; nt < 8; nt++) {
                int col = wn + nt * 8 + t2;
                if (r0 < M) {
                    __half2 hv = __floats2half2_rn(d[mt][nt][0] * n0, d[mt][nt][1] * n0);
                    *(__half2*)&g_linh[(size_t)r0 * HDIM + col] = hv;
                }
                if (r1 < M) {
                    __half2 hv = __floats2half2_rn(d[mt][nt][2] * n1, d[mt][nt][3] * n1);
                    *(__half2*)&g_linh[(size_t)r1 * HDIM + col] = hv;
                }
            }
        } else {
            #pragma unroll
            for (int nt = 0; nt < 8; nt++) {
                int col = wn + nt * 8 + t2;
                if (r0 < M)
                    *(float2*)(g_lin + (size_t)r0 * HDIM + col) = make_float2(d[mt][nt][0], d[mt][nt][1]);
                if (r1 < M)
                    *(float2*)(g_lin + (size_t)r1 * HDIM + col) = make_float2(d[mt][nt][2], d[mt][nt][3]);
            }
        }
    }
}

// ---------------- gather: h = relu(norm[dst]*(sum linh[src] + linh[dst]) + bias) ----------------
// One warp per dst row; lane owns 4 features (8B). Edge loop unrolled x8 (MLP=8).
__global__ __launch_bounds__(256) void gather_kernel(const float* __restrict__ bias, int M)
{
    int warp = (blockIdx.x * 256 + threadIdx.x) >> 5;
    int lane = threadIdx.x & 31;
    if (warp >= M) return;
    int row = warp;

    int start = g_rowstart[row];
    int end   = g_rowstart[row + 1];

    const uint2* lp = (const uint2*)g_linh;

    uint2 sv = __ldg(lp + (size_t)row * 32 + lane);
    float2 a01 = __half22float2(*(__half2*)&sv.x);
    float2 a23 = __half22float2(*(__half2*)&sv.y);
    float4 acc = make_float4(a01.x, a01.y, a23.x, a23.y);

    for (int bse = start; bse < end; bse += 32) {
        int idx = bse + lane;
        int sidx = (idx < end) ? g_csrS[idx] : 0;
        int cnt = min(32, end - bse);
        int j = 0;
        for (; j + 7 < cnt; j += 8) {
            uint2 v[8];
            #pragma unroll
            for (int u = 0; u < 8; u++) {
                int s = __shfl_sync(0xffffffffu, sidx, j + u);
                v[u] = __ldg(lp + (size_t)s * 32 + lane);
            }
            #pragma unroll
            for (int u = 0; u < 8; u++) {
                float2 p = __half22float2(*(__half2*)&v[u].x);
                float2 q = __half22float2(*(__half2*)&v[u].y);
                acc.x += p.x; acc.y += p.y; acc.z += q.x; acc.w += q.y;
            }
        }
        if (j + 3 < cnt) {
            uint2 v[4];
            #pragma unroll
            for (int u = 0; u < 4; u++) {
                int s = __shfl_sync(0xffffffffu, sidx, j + u);
                v[u] = __ldg(lp + (size_t)s * 32 + lane);
            }
            #pragma unroll
            for (int u = 0; u < 4; u++) {
                float2 p = __half22float2(*(__half2*)&v[u].x);
                float2 q = __half22float2(*(__half2*)&v[u].y);
                acc.x += p.x; acc.y += p.y; acc.z += q.x; acc.w += q.y;
            }
            j += 4;
        }
        for (; j < cnt; j++) {
            int s = __shfl_sync(0xffffffffu, sidx, j);
            uint2 v0 = __ldg(lp + (size_t)s * 32 + lane);
            float2 p = __half22float2(*(__half2*)&v0.x);
            float2 q = __half22float2(*(__half2*)&v0.y);
            acc.x += p.x; acc.y += p.y; acc.z += q.x; acc.w += q.y;
        }
    }

    float n = g_norm[row];
    float4 b4 = ((const float4*)bias)[lane];
    float4 h;
    h.x = fmaxf(fmaf(n, acc.x, b4.x), 0.f);
    h.y = fmaxf(fmaf(n, acc.y, b4.y), 0.f);
    h.z = fmaxf(fmaf(n, acc.z, b4.z), 0.f);
    h.w = fmaxf(fmaf(n, acc.w, b4.w), 0.f);
    ((float4*)g_h)[(size_t)row * 32 + lane] = h;
}

// ---------------- log_softmax ----------------
__global__ __launch_bounds__(256) void logsoftmax_kernel(float* __restrict__ out, int M)
{
    int warp = (blockIdx.x * 256 + threadIdx.x) >> 5;
    int lane = threadIdx.x & 31;
    if (warp >= M) return;
    int row = warp;

    const float* rp = g_lin + (size_t)row * HDIM;
    float l0 = rp[lane] + g_bf[lane];
    float l1 = (lane < 8) ? (rp[32 + lane] + g_bf[32 + lane]) : -1e30f;

    float m = fmaxf(l0, l1);
    #pragma unroll
    for (int o = 16; o > 0; o >>= 1) m = fmaxf(m, __shfl_xor_sync(0xffffffffu, m, o));

    float e = expf(l0 - m) + ((lane < 8) ? expf(l1 - m) : 0.f);
    #pragma unroll
    for (int o = 16; o > 0; o >>= 1) e += __shfl_xor_sync(0xffffffffu, e, o);

    float ls = m + logf(e);
    out[(size_t)row * CDIM + lane] = l0 - ls;
    if (lane < 8) out[(size_t)row * CDIM + 32 + lane] = l1 - ls;
}

// ---------------- launch ----------------
extern "C" void kernel_launch(void* const* d_in, const int* in_sizes, int n_in,
                              void* d_out, int out_size)
{
    const float* x   = (const float*)d_in[0];
    const void*  ei  = d_in[1];
    const float* W1  = (const float*)d_in[2];
    const float* b1  = (const float*)d_in[3];
    const float* W2  = (const float*)d_in[4];
    const float* b2  = (const float*)d_in[5];
    const float* W3  = (const float*)d_in[6];
    const float* b3  = (const float*)d_in[7];
    const float* Wp1 = (const float*)d_in[8];
    const float* bp1 = (const float*)d_in[9];
    const float* Wp2 = (const float*)d_in[10];
    const float* bp2 = (const float*)d_in[11];
    float* out = (float*)d_out;

    int M = in_sizes[0] / HDIM;
    int E = in_sizes[1] / 2;
    int nb = (M + 255) / 256;

    cudaFuncSetAttribute(mma_gemm_kernel,
                         cudaFuncAttributeMaxDynamicSharedMemorySize, GEMM_SMEM);

    init_kernel<<<nb, 256>>>(M);
    detect_kernel<<<128, 256>>>((const int*)ei, E);
    count_deg_kernel<<<(E + 255) / 256, 256>>>(ei, E);
    norm_bsum_kernel<<<nb, 256>>>(M);
    bscan_kernel<<<1, 512>>>(nb);
    rowstart_kernel<<<nb, 256>>>(M, E);
    csr_fill_kernel<<<(E + 255) / 256, 256>>>(ei, E);

    fuse_wb_kernel<<<(HDIM * CDIM + CDIM + 255) / 256, 256>>>(Wp1, bp1, Wp2, bp2);
    w_split_all_kernel<<<(3 * HDIM * HDIM + 255) / 256, 256>>>(W1, W2, W3);
    w_split_head_kernel<<<(HDIM * HDIM + 255) / 256, 256>>>();

    int gemmGrid   = (M + 127) / 128;
    int gatherGrid = (M + 7) / 8;

    mma_gemm_kernel<<<gemmGrid, 256, GEMM_SMEM>>>(x, M, 0, 0, 0);
    gather_kernel<<<gatherGrid, 256>>>(b1, M);
    mma_gemm_kernel<<<gemmGrid, 256, GEMM_SMEM>>>(nullptr, M, 1, 1, 0);
    gather_kernel<<<gatherGrid, 256>>>(b2, M);
    mma_gemm_kernel<<<gemmGrid, 256, GEMM_SMEM>>>(nullptr, M, 1, 2, 0);
    gather_kernel<<<gatherGrid, 256>>>(b3, M);

    mma_gemm_kernel<<<gemmGrid, 256, GEMM_SMEM>>>(nullptr, M, 1, 3, 1);
    logsoftmax_kernel<<<(M + 7) / 8, 256>>>(out, M);
}

// round 7
// speedup vs baseline: 1.1468x; 1.1468x over previous
#include <cuda_runtime.h>
#include <cuda_bf16.h>
#include <cuda_fp16.h>
#include <math.h>
#include <stdint.h>

#define MAXN 100000
#define MAXE 1600000
#define HDIM 128
#define CDIM 40
#define NBLK ((MAXN + 255) / 256)
#define PAD 136  // halves per smem row (128 + 8 pad -> conflict-free ldmatrix)

// ---------------- device scratch ----------------
__device__ __half g_linh[MAXN * HDIM];        // norm[row]*(h@W) fp16 (gather payload)
__device__ __half g_hh[MAXN * HDIM];          // layer output (post-ReLU) fp16
__device__ float  g_norm[MAXN];
__device__ int    g_deg[MAXN];
__device__ int    g_rowstart[MAXN + 1];
__device__ int    g_cursor[MAXN];
__device__ int    g_bsum[NBLK + 1];
__device__ int    g_csrS[MAXE];               // src index per edge, grouped by dst
__device__ float  g_Wf[HDIM * CDIM];
__device__ float  g_bf[CDIM];
__device__ int    g_any;
__device__ __nv_bfloat16 g_Bh[4 * HDIM * HDIM];  // W^T bf16 hi images (3 layers + head)
__device__ __nv_bfloat16 g_Bl[4 * HDIM * HDIM];  // lo residuals

// ---------------- PTX helpers ----------------
__device__ __forceinline__ uint32_t smem_u32(const void* p) {
    uint32_t a;
    asm("{ .reg .u64 t; cvta.to.shared.u64 t, %1; cvt.u32.u64 %0, t; }" : "=r"(a) : "l"(p));
    return a;
}
__device__ __forceinline__ void ldx4(uint32_t* r, uint32_t addr) {
    asm volatile("ldmatrix.sync.aligned.m8n8.x4.shared.b16 {%0,%1,%2,%3}, [%4];"
                 : "=r"(r[0]), "=r"(r[1]), "=r"(r[2]), "=r"(r[3]) : "r"(addr));
}
__device__ __forceinline__ void mma_bf16(float* d, const uint32_t* a, const uint32_t* b) {
    asm volatile("mma.sync.aligned.m16n8k16.row.col.f32.bf16.bf16.f32 "
                 "{%0,%1,%2,%3}, {%4,%5,%6,%7}, {%8,%9}, {%0,%1,%2,%3};"
                 : "+f"(d[0]), "+f"(d[1]), "+f"(d[2]), "+f"(d[3])
                 : "r"(a[0]), "r"(a[1]), "r"(a[2]), "r"(a[3]), "r"(b[0]), "r"(b[1]));
}
__device__ __forceinline__ int load_node(const void* ei, long long i, int is64) {
    if (is64) return (int)((const long long*)ei)[i];
    return ((const int*)ei)[i];
}

// ---------------- init / degree / norm / CSR ----------------
__global__ void init_kernel(int M) {
    int i = blockIdx.x * blockDim.x + threadIdx.x;
    if (i < M) g_deg[i] = 0;
    if (i == 0) g_any = 0;
}
__global__ void detect_kernel(const int* __restrict__ ei32, int nHalf) {
    int found = 0;
    for (int i = blockIdx.x * blockDim.x + threadIdx.x; i < nHalf; i += gridDim.x * blockDim.x)
        if (ei32[2 * i + 1] != 0) found = 1;
    if (found) atomicOr(&g_any, 1);
}
__global__ void count_deg_kernel(const void* __restrict__ ei, int E) {
    int is64 = (g_any == 0);
    int e = blockIdx.x * blockDim.x + threadIdx.x;
    if (e >= E) return;
    atomicAdd(&g_deg[load_node(ei, (long long)E + e, is64)], 1);
}
__global__ void norm_bsum_kernel(int M) {
    __shared__ int sd[256];
    int i = blockIdx.x * 256 + threadIdx.x;
    int d = (i < M) ? g_deg[i] : 0;
    if (i < M) g_norm[i] = rsqrtf((float)d + 1.0f);
    sd[threadIdx.x] = d;
    __syncthreads();
    for (int o = 128; o > 0; o >>= 1) {
        if (threadIdx.x < o) sd[threadIdx.x] += sd[threadIdx.x + o];
        __syncthreads();
    }
    if (threadIdx.x == 0) g_bsum[blockIdx.x] = sd[0];
}
__global__ void bscan_kernel(int nb) {
    __shared__ int sd[512];
    int t = threadIdx.x;
    int v = (t < nb) ? g_bsum[t] : 0;
    sd[t] = v;
    __syncthreads();
    for (int o = 1; o < 512; o <<= 1) {
        int x = (t >= o) ? sd[t - o] : 0;
        __syncthreads();
        sd[t] += x;
        __syncthreads();
    }
    if (t < nb) g_bsum[t] = sd[t] - v;
}
__global__ void rowstart_kernel(int M, int E) {
    __shared__ int sd[256];
    int i = blockIdx.x * 256 + threadIdx.x;
    int v = (i < M) ? g_deg[i] : 0;
    sd[threadIdx.x] = v;
    __syncthreads();
    for (int o = 1; o < 256; o <<= 1) {
        int t = (threadIdx.x >= o) ? sd[threadIdx.x - o] : 0;
        __syncthreads();
        sd[threadIdx.x] += t;
        __syncthreads();
    }
    if (i < M) {
        g_rowstart[i] = g_bsum[blockIdx.x] + sd[threadIdx.x] - v;
        g_cursor[i] = 0;
    }
    if (i == 0) g_rowstart[M] = E;
}
__global__ void csr_fill_kernel(const void* __restrict__ ei, int E) {
    int is64 = (g_any == 0);
    int e = blockIdx.x * blockDim.x + threadIdx.x;
    if (e >= E) return;
    int s = load_node(ei, e, is64);
    int d = load_node(ei, (long long)E + e, is64);
    int pos = g_rowstart[d] + atomicAdd(&g_cursor[d], 1);
    g_csrS[pos] = s;
}

// ---------------- fold MLP head ----------------
__global__ void fuse_wb_kernel(const float* __restrict__ Wp1, const float* __restrict__ bp1,
                               const float* __restrict__ Wp2, const float* __restrict__ bp2) {
    int id = blockIdx.x * blockDim.x + threadIdx.x;
    if (id < HDIM * CDIM) {
        int i = id / CDIM, c = id % CDIM;
        float s = 0.f;
        for (int j = 0; j < HDIM; j++)
            s = fmaf(Wp1[i * HDIM + j], Wp2[j * CDIM + c], s);
        g_Wf[id] = s;
    } else if (id < HDIM * CDIM + CDIM) {
        int c = id - HDIM * CDIM;
        float s = bp2[c];
        for (int j = 0; j < HDIM; j++)
            s = fmaf(bp1[j], Wp2[j * CDIM + c], s);
        g_bf[c] = s;
    }
}

// ---------------- W splits ----------------
__global__ void w_split_all_kernel(const float* __restrict__ W1, const float* __restrict__ W2,
                                   const float* __restrict__ W3) {
    int idx = blockIdx.x * 256 + threadIdx.x;
    if (idx >= 3 * HDIM * HDIM) return;
    int l = idx / (HDIM * HDIM);
    int r = idx - l * HDIM * HDIM;
    int n = r >> 7, k = r & 127;
    const float* W = (l == 0) ? W1 : (l == 1) ? W2 : W3;
    float v = W[k * HDIM + n];
    __nv_bfloat16 h = __float2bfloat16(v);
    g_Bh[idx] = h;
    g_Bl[idx] = __float2bfloat16(v - __bfloat162float(h));
}
__global__ void w_split_head_kernel() {
    int idx = blockIdx.x * 256 + threadIdx.x;
    if (idx >= HDIM * HDIM) return;
    int n = idx >> 7, k = idx & 127;
    float v = (n < CDIM) ? g_Wf[k * CDIM + n] : 0.f;
    __nv_bfloat16 h = __float2bfloat16(v);
    g_Bh[3 * HDIM * HDIM + idx] = h;
    g_Bl[3 * HDIM * HDIM + idx] = __float2bfloat16(v - __bfloat162float(h));
}

// ---------------- mma.sync GEMM (fp32 via bf16 hi/lo, 3 terms) ----------------
// mode 0: out = norm[row]*(A@W) -> g_linh (fp16)
// mode 1: head — logits + log_softmax fused, writes `out` directly
#define GEMM_SMEM (4 * 128 * PAD * 2)

__global__ __launch_bounds__(256) void mma_gemm_kernel(
    const float* __restrict__ A_ext, float* __restrict__ out,
    int M, int useInternal, int bsel, int mode)
{
    extern __shared__ __nv_bfloat16 sm[];
    __nv_bfloat16* sAh = sm;
    __nv_bfloat16* sAl = sm + 128 * PAD;
    __nv_bfloat16* sBh = sm + 2 * 128 * PAD;
    __nv_bfloat16* sBl = sm + 3 * 128 * PAD;
    const __nv_bfloat16* Bh = g_Bh + bsel * HDIM * HDIM;
    const __nv_bfloat16* Bl = g_Bl + bsel * HDIM * HDIM;

    int tid = threadIdx.x;
    int rowBase = blockIdx.x * 128;

    {
        const uint4* bh = (const uint4*)Bh;
        const uint4* bl = (const uint4*)Bl;
        for (int i = tid; i < 128 * 16; i += 256) {
            int n = i >> 4, c = i & 15;
            *(uint4*)(sBh + n * PAD + c * 8) = bh[i];
            *(uint4*)(sBl + n * PAD + c * 8) = bl[i];
        }
    }
    {
        int row = tid >> 1;
        int colBase = (tid & 1) * 64;
        int grow = rowBase + row;
        __nv_bfloat16* dh = sAh + row * PAD + colBase;
        __nv_bfloat16* dl = sAl + row * PAD + colBase;
        if (useInternal) {
            // fp16 source: split is exact (hi 8 mantissa bits + lo remainder)
            const uint4* Ap = (const uint4*)(g_hh + (size_t)grow * HDIM + colBase);
            #pragma unroll
            for (int j = 0; j < 8; j++) {
                uint4 v = make_uint4(0u, 0u, 0u, 0u);
                if (grow < M) v = Ap[j];
                const __half2* hp = (const __half2*)&v;
                #pragma unroll
                for (int p = 0; p < 4; p++) {
                    float2 f = __half22float2(hp[p]);
                    __nv_bfloat16 h0 = __float2bfloat16(f.x);
                    __nv_bfloat16 h1 = __float2bfloat16(f.y);
                    int o = j * 8 + p * 2;
                    dh[o] = h0; dh[o + 1] = h1;
                    dl[o] = __float2bfloat16(f.x - __bfloat162float(h0));
                    dl[o + 1] = __float2bfloat16(f.y - __bfloat162float(h1));
                }
            }
        } else {
            const float4* Ap = (const float4*)(A_ext + (size_t)grow * HDIM + colBase);
            #pragma unroll
            for (int j = 0; j < 16; j++) {
                float4 v = make_float4(0.f, 0.f, 0.f, 0.f);
                if (grow < M) v = Ap[j];
                __nv_bfloat16 h0 = __float2bfloat16(v.x);
                __nv_bfloat16 h1 = __float2bfloat16(v.y);
                __nv_bfloat16 h2 = __float2bfloat16(v.z);
                __nv_bfloat16 h3 = __float2bfloat16(v.w);
                dh[j * 4 + 0] = h0; dh[j * 4 + 1] = h1;
                dh[j * 4 + 2] = h2; dh[j * 4 + 3] = h3;
                dl[j * 4 + 0] = __float2bfloat16(v.x - __bfloat162float(h0));
                dl[j * 4 + 1] = __float2bfloat16(v.y - __bfloat162float(h1));
                dl[j * 4 + 2] = __float2bfloat16(v.z - __bfloat162float(h2));
                dl[j * 4 + 3] = __float2bfloat16(v.w - __bfloat162float(h3));
            }
        }
    }
    __syncthreads();

    int lane = tid & 31, wid = tid >> 5;
    int wm = (wid & 3) * 32;
    int wn = (wid >> 2) * 64;

    uint32_t sbase = smem_u32(sm);
    int a_r = lane & 15;
    int a_k = (lane >> 4) * 8;
    int b_n = ((lane >> 4) & 1) * 8 + (lane & 7);
    int b_k = ((lane >> 3) & 1) * 8;

    uint32_t aAh = sbase + ((wm + a_r) * PAD + a_k) * 2;
    uint32_t aAl = aAh + 128 * PAD * 2;
    uint32_t aBh = sbase + 2 * 128 * PAD * 2 + ((wn + b_n) * PAD + b_k) * 2;
    uint32_t aBl = aBh + 128 * PAD * 2;

    float d[2][8][4];
    #pragma unroll
    for (int mt = 0; mt < 2; mt++)
        #pragma unroll
        for (int nt = 0; nt < 8; nt++)
            #pragma unroll
            for (int r = 0; r < 4; r++) d[mt][nt][r] = 0.f;

    #pragma unroll
    for (int ks = 0; ks < 8; ks++) {
        uint32_t ah[2][4], al[2][4], bh[4][4], bl[4][4];
        uint32_t koff = (uint32_t)(ks * 16 * 2);
        #pragma unroll
        for (int mt = 0; mt < 2; mt++) {
            uint32_t moff = (uint32_t)(mt * 16 * PAD * 2) + koff;
            ldx4(ah[mt], aAh + moff);
            ldx4(al[mt], aAl + moff);
        }
        #pragma unroll
        for (int np = 0; np < 4; np++) {
            uint32_t noff = (uint32_t)(np * 16 * PAD * 2) + koff;
            ldx4(bh[np], aBh + noff);
            ldx4(bl[np], aBl + noff);
        }
        #pragma unroll
        for (int mt = 0; mt < 2; mt++) {
            #pragma unroll
            for (int nt = 0; nt < 8; nt++) {
                uint32_t* ph = &bh[nt >> 1][(nt & 1) * 2];
                uint32_t* pl = &bl[nt >> 1][(nt & 1) * 2];
                mma_bf16(d[mt][nt], ah[mt], ph);
                mma_bf16(d[mt][nt], ah[mt], pl);
                mma_bf16(d[mt][nt], al[mt], ph);
            }
        }
    }

    int g = lane >> 2, t2 = (lane & 3) * 2;
    if (mode == 0) {
        #pragma unroll
        for (int mt = 0; mt < 2; mt++) {
            int r0 = rowBase + wm + mt * 16 + g;
            int r1 = r0 + 8;
            float n0 = (r0 < M) ? g_norm[r0] : 0.f;
            float n1 = (r1 < M) ? g_norm[r1] : 0.f;
            #pragma unroll
            for (int nt = 0; nt < 8; nt++) {
                int col = wn + nt * 8 + t2;
                if (r0 < M) {
                    __half2 hv = __floats2half2_rn(d[mt][nt][0] * n0, d[mt][nt][1] * n0);
                    *(__half2*)&g_linh[(size_t)r0 * HDIM + col] = hv;
                }
                if (r1 < M) {
                    __half2 hv = __floats2half2_rn(d[mt][nt][2] * n1, d[mt][nt][3] * n1);
                    *(__half2*)&g_linh[(size_t)r1 * HDIM + col] = hv;
                }
            }
        }
    } else {
        // head: logits (cols 0..39) + bias + log_softmax, fused.
        // Row's 64 cols live in the 4-lane group {4g..4g+3}; only wn==0 warps hold cols<64.
        if (wn == 0) {
            float bv[5][2];
            #pragma unroll
            for (int nt = 0; nt < 5; nt++) {
                int col = nt * 8 + t2;
                bv[nt][0] = __ldg(g_bf + col);
                bv[nt][1] = __ldg(g_bf + col + 1);
            }
            #pragma unroll
            for (int mt = 0; mt < 2; mt++) {
                #pragma unroll
                for (int half = 0; half < 2; half++) {
                    int row = rowBase + wm + mt * 16 + g + half * 8;
                    int ri = half * 2;  // d[][][0,1] for r0, [2,3] for r1
                    float l[5][2];
                    float m = -1e30f;
                    #pragma unroll
                    for (int nt = 0; nt < 5; nt++) {
                        l[nt][0] = d[mt][nt][ri] + bv[nt][0];
                        l[nt][1] = d[mt][nt][ri + 1] + bv[nt][1];
                        m = fmaxf(m, fmaxf(l[nt][0], l[nt][1]));
                    }
                    m = fmaxf(m, __shfl_xor_sync(0xffffffffu, m, 1));
                    m = fmaxf(m, __shfl_xor_sync(0xffffffffu, m, 2));
                    float e = 0.f;
                    #pragma unroll
                    for (int nt = 0; nt < 5; nt++)
                        e += expf(l[nt][0] - m) + expf(l[nt][1] - m);
                    e += __shfl_xor_sync(0xffffffffu, e, 1);
                    e += __shfl_xor_sync(0xffffffffu, e, 2);
                    float ls = m + logf(e);
                    if (row < M) {
                        #pragma unroll
                        for (int nt = 0; nt < 5; nt++) {
                            int col = nt * 8 + t2;
                            *(float2*)(out + (size_t)row * CDIM + col) =
                                make_float2(l[nt][0] - ls, l[nt][1] - ls);
                        }
                    }
                }
            }
        }
    }
}

// ---------------- gather: h = relu(norm[dst]*(sum linh[src] + linh[dst]) + bias), fp16 out ----------------
__global__ __launch_bounds__(256) void gather_kernel(const float* __restrict__ bias, int M)
{
    int warp = (blockIdx.x * 256 + threadIdx.x) >> 5;
    int lane = threadIdx.x & 31;
    if (warp >= M) return;
    int row = warp;

    int start = g_rowstart[row];
    int end   = g_rowstart[row + 1];

    const uint2* lp = (const uint2*)g_linh;

    uint2 sv = __ldg(lp + (size_t)row * 32 + lane);
    float2 a01 = __half22float2(*(__half2*)&sv.x);
    float2 a23 = __half22float2(*(__half2*)&sv.y);
    float4 acc = make_float4(a01.x, a01.y, a23.x, a23.y);

    for (int bse = start; bse < end; bse += 32) {
        int idx = bse + lane;
        int sidx = (idx < end) ? g_csrS[idx] : 0;
        int cnt = min(32, end - bse);
        int j = 0;
        for (; j + 3 < cnt; j += 4) {
            uint2 v[4];
            #pragma unroll
            for (int u = 0; u < 4; u++) {
                int s = __shfl_sync(0xffffffffu, sidx, j + u);
                v[u] = __ldg(lp + (size_t)s * 32 + lane);
            }
            #pragma unroll
            for (int u = 0; u < 4; u++) {
                float2 p = __half22float2(*(__half2*)&v[u].x);
                float2 q = __half22float2(*(__half2*)&v[u].y);
                acc.x += p.x; acc.y += p.y; acc.z += q.x; acc.w += q.y;
            }
        }
        for (; j < cnt; j++) {
            int s = __shfl_sync(0xffffffffu, sidx, j);
            uint2 v0 = __ldg(lp + (size_t)s * 32 + lane);
            float2 p = __half22float2(*(__half2*)&v0.x);
            float2 q = __half22float2(*(__half2*)&v0.y);
            acc.x += p.x; acc.y += p.y; acc.z += q.x; acc.w += q.y;
        }
    }

    float n = g_norm[row];
    float4 b4 = ((const float4*)bias)[lane];
    float h0 = fmaxf(fmaf(n, acc.x, b4.x), 0.f);
    float h1 = fmaxf(fmaf(n, acc.y, b4.y), 0.f);
    float h2 = fmaxf(fmaf(n, acc.z, b4.z), 0.f);
    float h3 = fmaxf(fmaf(n, acc.w, b4.w), 0.f);
    uint2 hv;
    *(__half2*)&hv.x = __floats2half2_rn(h0, h1);
    *(__half2*)&hv.y = __floats2half2_rn(h2, h3);
    ((uint2*)g_hh)[(size_t)row * 32 + lane] = hv;
}

// ---------------- launch ----------------
extern "C" void kernel_launch(void* const* d_in, const int* in_sizes, int n_in,
                              void* d_out, int out_size)
{
    const float* x   = (const float*)d_in[0];
    const void*  ei  = d_in[1];
    const float* W1  = (const float*)d_in[2];
    const float* b1  = (const float*)d_in[3];
    const float* W2  = (const float*)d_in[4];
    const float* b2  = (const float*)d_in[5];
    const float* W3  = (const float*)d_in[6];
    const float* b3  = (const float*)d_in[7];
    const float* Wp1 = (const float*)d_in[8];
    const float* bp1 = (const float*)d_in[9];
    const float* Wp2 = (const float*)d_in[10];
    const float* bp2 = (const float*)d_in[11];
    float* out = (float*)d_out;

    int M = in_sizes[0] / HDIM;
    int E = in_sizes[1] / 2;
    int nb = (M + 255) / 256;

    cudaFuncSetAttribute(mma_gemm_kernel,
                         cudaFuncAttributeMaxDynamicSharedMemorySize, GEMM_SMEM);

    init_kernel<<<nb, 256>>>(M);
    detect_kernel<<<128, 256>>>((const int*)ei, E);
    count_deg_kernel<<<(E + 255) / 256, 256>>>(ei, E);
    norm_bsum_kernel<<<nb, 256>>>(M);
    bscan_kernel<<<1, 512>>>(nb);
    rowstart_kernel<<<nb, 256>>>(M, E);
    csr_fill_kernel<<<(E + 255) / 256, 256>>>(ei, E);

    fuse_wb_kernel<<<(HDIM * CDIM + CDIM + 255) / 256, 256>>>(Wp1, bp1, Wp2, bp2);
    w_split_all_kernel<<<(3 * HDIM * HDIM + 255) / 256, 256>>>(W1, W2, W3);
    w_split_head_kernel<<<(HDIM * HDIM + 255) / 256, 256>>>();

    int gemmGrid   = (M + 127) / 128;
    int gatherGrid = (M + 7) / 8;

    mma_gemm_kernel<<<gemmGrid, 256, GEMM_SMEM>>>(x, out, M, 0, 0, 0);
    gather_kernel<<<gatherGrid, 256>>>(b1, M);
    mma_gemm_kernel<<<gemmGrid, 256, GEMM_SMEM>>>(nullptr, out, M, 1, 1, 0);
    gather_kernel<<<gatherGrid, 256>>>(b2, M);
    mma_gemm_kernel<<<gemmGrid, 256, GEMM_SMEM>>>(nullptr, out, M, 1, 2, 0);
    gather_kernel<<<gatherGrid, 256>>>(b3, M);

    mma_gemm_kernel<<<gemmGrid, 256, GEMM_SMEM>>>(nullptr, out, M, 1, 3, 1);
}

// round 8
// speedup vs baseline: 1.4298x; 1.2468x over previous
#include <cuda_runtime.h>
#include <cuda_fp16.h>
#include <math.h>
#include <stdint.h>

#define MAXN 100000
#define MAXE 1600000
#define HDIM 128
#define CDIM 40
#define NBLK ((MAXN + 255) / 256)
#define PAD 136  // halves per smem row (128 + 8 pad -> conflict-free ldmatrix)

// ---------------- device scratch ----------------
__device__ __half g_linh[MAXN * HDIM];        // norm[row]*(h@W) fp16 (gather payload)
__device__ __half g_hh[MAXN * HDIM];          // layer output (post-ReLU) fp16
__device__ float  g_norm[MAXN];
__device__ int    g_deg[MAXN];
__device__ int    g_rowstart[MAXN + 1];
__device__ int    g_cursor[MAXN];
__device__ int    g_bsum[NBLK + 1];
__device__ int    g_csrS[MAXE];               // src index per edge, grouped by dst
__device__ float  g_bf[CDIM];
__device__ int    g_any;
__device__ __half g_Wh[4 * HDIM * HDIM];      // W^T fp16 hi images (3 layers + head)
__device__ __half g_Wl[4 * HDIM * HDIM];      // fp16( 2048*(W - hi) )

// ---------------- PTX helpers ----------------
__device__ __forceinline__ uint32_t smem_u32(const void* p) {
    uint32_t a;
    asm("{ .reg .u64 t; cvta.to.shared.u64 t, %1; cvt.u32.u64 %0, t; }" : "=r"(a) : "l"(p));
    return a;
}
__device__ __forceinline__ void ldx4(uint32_t* r, uint32_t addr) {
    asm volatile("ldmatrix.sync.aligned.m8n8.x4.shared.b16 {%0,%1,%2,%3}, [%4];"
                 : "=r"(r[0]), "=r"(r[1]), "=r"(r[2]), "=r"(r[3]) : "r"(addr));
}
__device__ __forceinline__ void mma_f16(float* d, const uint32_t* a, const uint32_t* b) {
    asm volatile("mma.sync.aligned.m16n8k16.row.col.f32.f16.f16.f32 "
                 "{%0,%1,%2,%3}, {%4,%5,%6,%7}, {%8,%9}, {%0,%1,%2,%3};"
                 : "+f"(d[0]), "+f"(d[1]), "+f"(d[2]), "+f"(d[3])
                 : "r"(a[0]), "r"(a[1]), "r"(a[2]), "r"(a[3]), "r"(b[0]), "r"(b[1]));
}
__device__ __forceinline__ int load_node(const void* ei, long long i, int is64) {
    if (is64) return (int)((const long long*)ei)[i];
    return ((const int*)ei)[i];
}

// ---------------- init + dtype detect (merged) ----------------
__global__ void init_detect_kernel(const int* __restrict__ ei32, int M, int nHalf) {
    int i = blockIdx.x * blockDim.x + threadIdx.x;
    if (i < M) g_deg[i] = 0;
    if (i == 0) g_any = 0;
    int found = 0;
    for (int j = i; j < nHalf; j += gridDim.x * blockDim.x)
        if (ei32[2 * j + 1] != 0) found = 1;
    if (found) atomicOr(&g_any, 1);
}
__global__ void count_deg_kernel(const void* __restrict__ ei, int E) {
    int is64 = (g_any == 0);
    int e = blockIdx.x * blockDim.x + threadIdx.x;
    if (e >= E) return;
    atomicAdd(&g_deg[load_node(ei, (long long)E + e, is64)], 1);
}
__global__ void norm_bsum_kernel(int M) {
    __shared__ int sd[256];
    int i = blockIdx.x * 256 + threadIdx.x;
    int d = (i < M) ? g_deg[i] : 0;
    if (i < M) g_norm[i] = rsqrtf((float)d + 1.0f);
    sd[threadIdx.x] = d;
    __syncthreads();
    for (int o = 128; o > 0; o >>= 1) {
        if (threadIdx.x < o) sd[threadIdx.x] += sd[threadIdx.x + o];
        __syncthreads();
    }
    if (threadIdx.x == 0) g_bsum[blockIdx.x] = sd[0];
}
__global__ void bscan_kernel(int nb) {
    __shared__ int sd[512];
    int t = threadIdx.x;
    int v = (t < nb) ? g_bsum[t] : 0;
    sd[t] = v;
    __syncthreads();
    for (int o = 1; o < 512; o <<= 1) {
        int x = (t >= o) ? sd[t - o] : 0;
        __syncthreads();
        sd[t] += x;
        __syncthreads();
    }
    if (t < nb) g_bsum[t] = sd[t] - v;
}
__global__ void rowstart_kernel(int M, int E) {
    __shared__ int sd[256];
    int i = blockIdx.x * 256 + threadIdx.x;
    int v = (i < M) ? g_deg[i] : 0;
    sd[threadIdx.x] = v;
    __syncthreads();
    for (int o = 1; o < 256; o <<= 1) {
        int t = (threadIdx.x >= o) ? sd[threadIdx.x - o] : 0;
        __syncthreads();
        sd[threadIdx.x] += t;
        __syncthreads();
    }
    if (i < M) {
        g_rowstart[i] = g_bsum[blockIdx.x] + sd[threadIdx.x] - v;
        g_cursor[i] = 0;
    }
    if (i == 0) g_rowstart[M] = E;
}
__global__ void csr_fill_kernel(const void* __restrict__ ei, int E) {
    int is64 = (g_any == 0);
    int e = blockIdx.x * blockDim.x + threadIdx.x;
    if (e >= E) return;
    int s = load_node(ei, e, is64);
    int d = load_node(ei, (long long)E + e, is64);
    int pos = g_rowstart[d] + atomicAdd(&g_cursor[d], 1);
    g_csrS[pos] = s;
}

// ---------------- W splits (layers 1-3): slot l, [n][k] = W[k][n] ----------------
__global__ void w_split_all_kernel(const float* __restrict__ W1, const float* __restrict__ W2,
                                   const float* __restrict__ W3) {
    int idx = blockIdx.x * 256 + threadIdx.x;
    if (idx >= 3 * HDIM * HDIM) return;
    int l = idx / (HDIM * HDIM);
    int r = idx - l * HDIM * HDIM;
    int n = r >> 7, k = r & 127;
    const float* W = (l == 0) ? W1 : (l == 1) ? W2 : W3;
    float v = W[k * HDIM + n];
    __half h = __float2half_rn(v);
    g_Wh[idx] = h;
    g_Wl[idx] = __float2half_rn((v - __half2float(h)) * 2048.0f);
}
// head: fold Wf = Wp1@Wp2 and split directly into slot 3 (zero-padded); bias bf = bp1@Wp2+bp2
__global__ void fuse_head_kernel(const float* __restrict__ Wp1, const float* __restrict__ bp1,
                                 const float* __restrict__ Wp2, const float* __restrict__ bp2) {
    int id = blockIdx.x * blockDim.x + threadIdx.x;
    if (id < HDIM * HDIM) {
        int n = id >> 7, k = id & 127;
        float v = 0.f;
        if (n < CDIM) {
            for (int j = 0; j < HDIM; j++)
                v = fmaf(Wp1[k * HDIM + j], Wp2[j * CDIM + n], v);
        }
        __half h = __float2half_rn(v);
        g_Wh[3 * HDIM * HDIM + id] = h;
        g_Wl[3 * HDIM * HDIM + id] = __float2half_rn((v - __half2float(h)) * 2048.0f);
    } else if (id < HDIM * HDIM + CDIM) {
        int c = id - HDIM * HDIM;
        float s = bp2[c];
        for (int j = 0; j < HDIM; j++)
            s = fmaf(bp1[j], Wp2[j * CDIM + c], s);
        g_bf[c] = s;
    }
}

// ---------------- mma.sync GEMM: 2-term fp16 (A·Wh + (A*2^-11)·(Wl*2^11)) ----------------
// mode 0: out = norm[row]*(A@W) -> g_linh (fp16)
// mode 1: head — logits + log_softmax fused, writes `out` directly
#define GEMM_SMEM (3 * 128 * PAD * 2)

__global__ __launch_bounds__(256, 2) void mma_gemm_kernel(
    const float* __restrict__ A_ext, float* __restrict__ out,
    int M, int useInternal, int bsel, int mode)
{
    extern __shared__ __half sm[];
    __half* sA  = sm;                 // [128][PAD] fp16
    __half* sBh = sm + 128 * PAD;
    __half* sBl = sm + 2 * 128 * PAD;
    const __half* Bh = g_Wh + bsel * HDIM * HDIM;
    const __half* Bl = g_Wl + bsel * HDIM * HDIM;

    int tid = threadIdx.x;
    int rowBase = blockIdx.x * 128;

    // copy W images (32KB each)
    {
        const uint4* bh = (const uint4*)Bh;
        const uint4* bl = (const uint4*)Bl;
        for (int i = tid; i < 128 * 16; i += 256) {
            int n = i >> 4, c = i & 15;
            *(uint4*)(sBh + n * PAD + c * 8) = bh[i];
            *(uint4*)(sBl + n * PAD + c * 8) = bl[i];
        }
    }
    // A fill: half row per thread (64 elems)
    {
        int row = tid >> 1;
        int colBase = (tid & 1) * 64;
        int grow = rowBase + row;
        __half* dst = sA + row * PAD + colBase;
        if (useInternal) {
            const uint4* Ap = (const uint4*)(g_hh + (size_t)grow * HDIM + colBase);
            #pragma unroll
            for (int j = 0; j < 8; j++) {
                uint4 v = make_uint4(0u, 0u, 0u, 0u);
                if (grow < M) v = Ap[j];
                *(uint4*)(dst + j * 8) = v;
            }
        } else {
            const float4* Ap = (const float4*)(A_ext + (size_t)grow * HDIM + colBase);
            #pragma unroll
            for (int j = 0; j < 16; j++) {
                float4 v = make_float4(0.f, 0.f, 0.f, 0.f);
                if (grow < M) v = Ap[j];
                __half2 h01 = __floats2half2_rn(v.x, v.y);
                __half2 h23 = __floats2half2_rn(v.z, v.w);
                *(__half2*)(dst + j * 4)     = h01;
                *(__half2*)(dst + j * 4 + 2) = h23;
            }
        }
    }
    __syncthreads();

    int lane = tid & 31, wid = tid >> 5;
    int wm = (wid & 3) * 32;
    int wn = (wid >> 2) * 64;

    uint32_t sbase = smem_u32(sm);
    int a_r = lane & 15;
    int a_k = (lane >> 4) * 8;
    int b_n = ((lane >> 4) & 1) * 8 + (lane & 7);
    int b_k = ((lane >> 3) & 1) * 8;

    uint32_t aA  = sbase + ((wm + a_r) * PAD + a_k) * 2;
    uint32_t aBh = sbase + 128 * PAD * 2 + ((wn + b_n) * PAD + b_k) * 2;
    uint32_t aBl = aBh + 128 * PAD * 2;

    const __half2 SC = __float2half2_rn(4.8828125e-4f);  // 2^-11
    const uint32_t scu = *(const uint32_t*)&SC;

    float d[2][8][4];
    #pragma unroll
    for (int mt = 0; mt < 2; mt++)
        #pragma unroll
        for (int nt = 0; nt < 8; nt++)
            #pragma unroll
            for (int r = 0; r < 4; r++) d[mt][nt][r] = 0.f;

    #pragma unroll
    for (int ks = 0; ks < 8; ks++) {
        uint32_t a[2][4], as[2][4], b[4][4];
        uint32_t koff = (uint32_t)(ks * 16 * 2);
        #pragma unroll
        for (int mt = 0; mt < 2; mt++) {
            ldx4(a[mt], aA + (uint32_t)(mt * 16 * PAD * 2) + koff);
            #pragma unroll
            for (int r = 0; r < 4; r++) {
                __half2 av = *(__half2*)&a[mt][r];
                __half2 sv = __hmul2(av, *(const __half2*)&scu);
                as[mt][r] = *(uint32_t*)&sv;
            }
        }
        // hi term
        #pragma unroll
        for (int np = 0; np < 4; np++)
            ldx4(b[np], aBh + (uint32_t)(np * 16 * PAD * 2) + koff);
        #pragma unroll
        for (int mt = 0; mt < 2; mt++)
            #pragma unroll
            for (int nt = 0; nt < 8; nt++)
                mma_f16(d[mt][nt], a[mt], &b[nt >> 1][(nt & 1) * 2]);
        // lo term (scaled A)
        #pragma unroll
        for (int np = 0; np < 4; np++)
            ldx4(b[np], aBl + (uint32_t)(np * 16 * PAD * 2) + koff);
        #pragma unroll
        for (int mt = 0; mt < 2; mt++)
            #pragma unroll
            for (int nt = 0; nt < 8; nt++)
                mma_f16(d[mt][nt], as[mt], &b[nt >> 1][(nt & 1) * 2]);
    }

    int g = lane >> 2, t2 = (lane & 3) * 2;
    if (mode == 0) {
        #pragma unroll
        for (int mt = 0; mt < 2; mt++) {
            int r0 = rowBase + wm + mt * 16 + g;
            int r1 = r0 + 8;
            float n0 = (r0 < M) ? g_norm[r0] : 0.f;
            float n1 = (r1 < M) ? g_norm[r1] : 0.f;
            #pragma unroll
            for (int nt = 0; nt < 8; nt++) {
                int col = wn + nt * 8 + t2;
                if (r0 < M) {
                    __half2 hv = __floats2half2_rn(d[mt][nt][0] * n0, d[mt][nt][1] * n0);
                    *(__half2*)&g_linh[(size_t)r0 * HDIM + col] = hv;
                }
                if (r1 < M) {
                    __half2 hv = __floats2half2_rn(d[mt][nt][2] * n1, d[mt][nt][3] * n1);
                    *(__half2*)&g_linh[(size_t)r1 * HDIM + col] = hv;
                }
            }
        }
    } else {
        if (wn == 0) {
            float bv[5][2];
            #pragma unroll
            for (int nt = 0; nt < 5; nt++) {
                int col = nt * 8 + t2;
                bv[nt][0] = __ldg(g_bf + col);
                bv[nt][1] = __ldg(g_bf + col + 1);
            }
            #pragma unroll
            for (int mt = 0; mt < 2; mt++) {
                #pragma unroll
                for (int half = 0; half < 2; half++) {
                    int row = rowBase + wm + mt * 16 + g + half * 8;
                    int ri = half * 2;
                    float l[5][2];
                    float m = -1e30f;
                    #pragma unroll
                    for (int nt = 0; nt < 5; nt++) {
                        l[nt][0] = d[mt][nt][ri] + bv[nt][0];
                        l[nt][1] = d[mt][nt][ri + 1] + bv[nt][1];
                        m = fmaxf(m, fmaxf(l[nt][0], l[nt][1]));
                    }
                    m = fmaxf(m, __shfl_xor_sync(0xffffffffu, m, 1));
                    m = fmaxf(m, __shfl_xor_sync(0xffffffffu, m, 2));
                    float e = 0.f;
                    #pragma unroll
                    for (int nt = 0; nt < 5; nt++)
                        e += expf(l[nt][0] - m) + expf(l[nt][1] - m);
                    e += __shfl_xor_sync(0xffffffffu, e, 1);
                    e += __shfl_xor_sync(0xffffffffu, e, 2);
                    float ls = m + logf(e);
                    if (row < M) {
                        #pragma unroll
                        for (int nt = 0; nt < 5; nt++) {
                            int col = nt * 8 + t2;
                            *(float2*)(out + (size_t)row * CDIM + col) =
                                make_float2(l[nt][0] - ls, l[nt][1] - ls);
                        }
                    }
                }
            }
        }
    }
}

// ---------------- gather: h = relu(norm[dst]*(sum linh[src] + linh[dst]) + bias), fp16 out ----------------
__global__ __launch_bounds__(256) void gather_kernel(const float* __restrict__ bias, int M)
{
    int warp = (blockIdx.x * 256 + threadIdx.x) >> 5;
    int lane = threadIdx.x & 31;
    if (warp >= M) return;
    int row = warp;

    int start = g_rowstart[row];
    int end   = g_rowstart[row + 1];

    const uint2* lp = (const uint2*)g_linh;

    uint2 sv = __ldg(lp + (size_t)row * 32 + lane);
    float2 a01 = __half22float2(*(__half2*)&sv.x);
    float2 a23 = __half22float2(*(__half2*)&sv.y);
    float4 acc = make_float4(a01.x, a01.y, a23.x, a23.y);

    for (int bse = start; bse < end; bse += 32) {
        int idx = bse + lane;
        int sidx = (idx < end) ? g_csrS[idx] : 0;
        int cnt = min(32, end - bse);
        int j = 0;
        for (; j + 3 < cnt; j += 4) {
            uint2 v[4];
            #pragma unroll
            for (int u = 0; u < 4; u++) {
                int s = __shfl_sync(0xffffffffu, sidx, j + u);
                v[u] = __ldg(lp + (size_t)s * 32 + lane);
            }
            #pragma unroll
            for (int u = 0; u < 4; u++) {
                float2 p = __half22float2(*(__half2*)&v[u].x);
                float2 q = __half22float2(*(__half2*)&v[u].y);
                acc.x += p.x; acc.y += p.y; acc.z += q.x; acc.w += q.y;
            }
        }
        for (; j < cnt; j++) {
            int s = __shfl_sync(0xffffffffu, sidx, j);
            uint2 v0 = __ldg(lp + (size_t)s * 32 + lane);
            float2 p = __half22float2(*(__half2*)&v0.x);
            float2 q = __half22float2(*(__half2*)&v0.y);
            acc.x += p.x; acc.y += p.y; acc.z += q.x; acc.w += q.y;
        }
    }

    float n = g_norm[row];
    float4 b4 = ((const float4*)bias)[lane];
    float h0 = fmaxf(fmaf(n, acc.x, b4.x), 0.f);
    float h1 = fmaxf(fmaf(n, acc.y, b4.y), 0.f);
    float h2 = fmaxf(fmaf(n, acc.z, b4.z), 0.f);
    float h3 = fmaxf(fmaf(n, acc.w, b4.w), 0.f);
    uint2 hv;
    *(__half2*)&hv.x = __floats2half2_rn(h0, h1);
    *(__half2*)&hv.y = __floats2half2_rn(h2, h3);
    ((uint2*)g_hh)[(size_t)row * 32 + lane] = hv;
}

// ---------------- launch ----------------
extern "C" void kernel_launch(void* const* d_in, const int* in_sizes, int n_in,
                              void* d_out, int out_size)
{
    const float* x   = (const float*)d_in[0];
    const void*  ei  = d_in[1];
    const float* W1  = (const float*)d_in[2];
    const float* b1  = (const float*)d_in[3];
    const float* W2  = (const float*)d_in[4];
    const float* b2  = (const float*)d_in[5];
    const float* W3  = (const float*)d_in[6];
    const float* b3  = (const float*)d_in[7];
    const float* Wp1 = (const float*)d_in[8];
    const float* bp1 = (const float*)d_in[9];
    const float* Wp2 = (const float*)d_in[10];
    const float* bp2 = (const float*)d_in[11];
    float* out = (float*)d_out;

    int M = in_sizes[0] / HDIM;
    int E = in_sizes[1] / 2;
    int nb = (M + 255) / 256;

    cudaFuncSetAttribute(mma_gemm_kernel,
                         cudaFuncAttributeMaxDynamicSharedMemorySize, GEMM_SMEM);

    init_detect_kernel<<<nb, 256>>>((const int*)ei, M, E);
    count_deg_kernel<<<(E + 255) / 256, 256>>>(ei, E);
    norm_bsum_kernel<<<nb, 256>>>(M);
    bscan_kernel<<<1, 512>>>(nb);
    rowstart_kernel<<<nb, 256>>>(M, E);
    csr_fill_kernel<<<(E + 255) / 256, 256>>>(ei, E);

    w_split_all_kernel<<<(3 * HDIM * HDIM + 255) / 256, 256>>>(W1, W2, W3);
    fuse_head_kernel<<<(HDIM * HDIM + CDIM + 255) / 256, 256>>>(Wp1, bp1, Wp2, bp2);

    int gemmGrid   = (M + 127) / 128;
    int gatherGrid = (M + 7) / 8;

    mma_gemm_kernel<<<gemmGrid, 256, GEMM_SMEM>>>(x, out, M, 0, 0, 0);
    gather_kernel<<<gatherGrid, 256>>>(b1, M);
    mma_gemm_kernel<<<gemmGrid, 256, GEMM_SMEM>>>(nullptr, out, M, 1, 1, 0);
    gather_kernel<<<gatherGrid, 256>>>(b2, M);
    mma_gemm_kernel<<<gemmGrid, 256, GEMM_SMEM>>>(nullptr, out, M, 1, 2, 0);
    gather_kernel<<<gatherGrid, 256>>>(b3, M);

    mma_gemm_kernel<<<gemmGrid, 256, GEMM_SMEM>>>(nullptr, out, M, 1, 3, 1);
}